// round 11
// baseline (speedup 1.0000x reference)
#include <cuda_runtime.h>
#include <cstdint>

// (B, N, T, H) = (16, 256, 96, 128)
#define BB 16
#define NN 256
#define TT 96
#define HH 128
#define EPS 1e-5f
#define NPAIR (BB * NN)        // 4096

// Scratch (static __device__ — allocation-free)
__device__ float  g_C[TT * HH];        // time_emb @ W3            (48 KB)
__device__ float  g_nodeS[NN * HH];    // node_emb @ W2            (128 KB)
__device__ float  g_Wf[TT * HH];       // Wp @ W1  (fused proj)    (48 KB)
__device__ float  g_bias[HH];          // bp @ W1 + bf
__device__ float  g_A[NPAIR * HH];     // x@Wf + bias + nodeS      (2 MB)
__device__ float2 g_stats[NPAIR * TT]; // per-row (mean, rstd)     (3 MB)

// ---------------------------------------------------------------------------
// Prep kernel: tiny GEMMs. 449 blocks x 512 threads, 4-way split-K.
// ---------------------------------------------------------------------------
__global__ __launch_bounds__(512) void prep_kernel(
    const float* __restrict__ Wp,
    const float* __restrict__ bp,
    const float* __restrict__ Wf,
    const float* __restrict__ bf,
    const float* __restrict__ node_emb,
    const float* __restrict__ time_emb) {

    __shared__ float vsh[HH];
    __shared__ float partial[4][HH];

    const int r = blockIdx.x;
    const int k = threadIdx.x & (HH - 1);
    const int p = threadIdx.x >> 7;       // 0..3

    const float* __restrict__ v;
    const float* __restrict__ W;
    if (r < TT)                { v = time_emb + r * HH;        W = Wf + 2 * HH * HH; }
    else if (r < 2 * TT)       { v = Wp + (r - TT) * HH;       W = Wf; }
    else if (r < 2 * TT + NN)  { v = node_emb + (r - 2*TT)*HH; W = Wf + HH * HH; }
    else                       { v = bp;                       W = Wf; }

    if (threadIdx.x < HH) vsh[threadIdx.x] = v[threadIdx.x];
    __syncthreads();

    float acc = 0.f;
    const int h0 = p * 32;
#pragma unroll
    for (int hh = 0; hh < 32; hh++) {
        const int h = h0 + hh;
        acc += vsh[h] * W[h * HH + k];   // coalesced over k
    }
    partial[p][k] = acc;
    __syncthreads();

    if (threadIdx.x < HH) {
        float s = partial[0][k] + partial[1][k] + partial[2][k] + partial[3][k];
        if (r < TT)               g_C[r * HH + k] = s;
        else if (r < 2 * TT)      g_Wf[(r - TT) * HH + k] = s;
        else if (r < 2 * TT + NN) g_nodeS[(r - 2 * TT) * HH + k] = s;
        else                      g_bias[k] = s + bf[k];
    }
}

// ---------------------------------------------------------------------------
// GEMM-A kernel: g_A[pair,k] = bias[k] + nodeS[pair&255,k]
//                            + sum_t x[pair,t] * Wfused[t,k]
// 256 blocks x 256 threads, 16 pairs per block, 8 pairs x 1 col per thread.
// ---------------------------------------------------------------------------
__global__ __launch_bounds__(256) void gemmA_kernel(const float* __restrict__ x) {
    __shared__ float xsT[TT][16];     // transposed x tile, 6 KB

    const int pair0 = blockIdx.x * 16;
    const int tid   = threadIdx.x;

    for (int idx = tid; idx < 16 * TT; idx += 256) {
        const int pl = idx / TT;
        const int t  = idx - pl * TT;
        xsT[t][pl] = x[(size_t)(pair0 + pl) * TT + t];
    }
    __syncthreads();

    const int k   = tid & (HH - 1);
    const int pl0 = (tid >> 7) * 8;   // 0 or 8

    float acc[8] = {0.f, 0.f, 0.f, 0.f, 0.f, 0.f, 0.f, 0.f};
#pragma unroll 4
    for (int t = 0; t < TT; t++) {
        const float wv = g_Wf[t * HH + k];
        const float4 xa = *reinterpret_cast<const float4*>(&xsT[t][pl0]);
        const float4 xb = *reinterpret_cast<const float4*>(&xsT[t][pl0 + 4]);
        acc[0] += wv * xa.x;  acc[1] += wv * xa.y;
        acc[2] += wv * xa.z;  acc[3] += wv * xa.w;
        acc[4] += wv * xb.x;  acc[5] += wv * xb.y;
        acc[6] += wv * xb.z;  acc[7] += wv * xb.w;
    }

    const float bias = __ldg(g_bias + k);
#pragma unroll
    for (int pl = 0; pl < 8; pl++) {
        const int pair = pair0 + pl0 + pl;
        const int n    = pair & (NN - 1);
        g_A[(size_t)pair * HH + k] = acc[pl] + bias + __ldg(g_nodeS + n * HH + k);
    }
}

// ---------------------------------------------------------------------------
// Stats kernel: g_stats[pair*96+t] = (mean, rstd) of relu(A[pair]+C[t]).
// 4096 blocks x 128 threads (4 warps); warp w owns rows [24w, 24w+24) as
// 12 passes of 2 rows. 16 lanes per row: lane il owns cols {4il} and
// {64+4il}; 4-round shfl butterfly inside each 16-lane half. All cross-lane
// reductions of the whole pipeline live HERE, writing only 3 MB.
// ---------------------------------------------------------------------------
__global__ __launch_bounds__(128, 8) void stats_kernel() {
    const int pair = blockIdx.x;
    const int tid  = threadIdx.x;
    const int w    = tid >> 5;
    const int l    = tid & 31;
    const int rgrp = l >> 4;
    const int il   = l & 15;
    const int col0 = 4 * il;

    const float* __restrict__ arow = g_A + (size_t)pair * HH;
    const float4 a0 = __ldg(reinterpret_cast<const float4*>(arow + col0));
    const float4 a1 = __ldg(reinterpret_cast<const float4*>(arow + 64 + col0));

#pragma unroll 2
    for (int p = 0; p < 12; p++) {
        const int row = w * 24 + p * 2 + rgrp;
        const float* __restrict__ crow = g_C + row * HH;
        const float4 c0 = __ldg(reinterpret_cast<const float4*>(crow + col0));
        const float4 c1 = __ldg(reinterpret_cast<const float4*>(crow + 64 + col0));

        float4 v0, v1;
        v0.x = fmaxf(a0.x + c0.x, 0.f);
        v0.y = fmaxf(a0.y + c0.y, 0.f);
        v0.z = fmaxf(a0.z + c0.z, 0.f);
        v0.w = fmaxf(a0.w + c0.w, 0.f);
        v1.x = fmaxf(a1.x + c1.x, 0.f);
        v1.y = fmaxf(a1.y + c1.y, 0.f);
        v1.z = fmaxf(a1.z + c1.z, 0.f);
        v1.w = fmaxf(a1.w + c1.w, 0.f);

        float s1 = v0.x + v0.y + v0.z + v0.w
                 + v1.x + v1.y + v1.z + v1.w;
        float s2 = v0.x * v0.x + v0.y * v0.y + v0.z * v0.z + v0.w * v0.w
                 + v1.x * v1.x + v1.y * v1.y + v1.z * v1.z + v1.w * v1.w;

#pragma unroll
        for (int off = 1; off < 16; off <<= 1) {
            s1 += __shfl_xor_sync(0xffffffffu, s1, off);
            s2 += __shfl_xor_sync(0xffffffffu, s2, off);
        }

        if (il == 0) {
            const float mean = s1 * (1.f / HH);
            const float var  = s2 * (1.f / HH) - mean * mean;
            g_stats[pair * TT + row] = make_float2(mean, rsqrtf(var + EPS));
        }
    }
}

// ---------------------------------------------------------------------------
// Store kernel: PURE FEED-FORWARD STREAMING — no shfl, no smem, no syncs.
// 2048 blocks x 256 threads; block = 2 pairs, 4 warps per pair, warp owns
// 24 rows. One warp = one full 128-float row per iteration (lane l owns
// cols 4l..4l+4): per row 1 L1-hot C LDG.128 + 1 broadcast stats LDG.64 +
// ~20 ALU + 1 STG.128 (__stcs, evict-first). All iterations independent.
// ---------------------------------------------------------------------------
__global__ __launch_bounds__(256, 6) void store_kernel(
    const float* __restrict__ gamma,
    const float* __restrict__ beta,
    float* __restrict__ out) {

    const int tid  = threadIdx.x;
    const int w    = tid >> 5;
    const int l    = tid & 31;
    const int pair = blockIdx.x * 2 + (w >> 2);
    const int sub  = w & 3;
    const int col0 = 4 * l;           // 32 lanes x 4 = full 128-wide row

    const float4 a  = __ldg(reinterpret_cast<const float4*>(g_A + (size_t)pair * HH + col0));
    const float4 gg = __ldg(reinterpret_cast<const float4*>(gamma + col0));
    const float4 bb = __ldg(reinterpret_cast<const float4*>(beta + col0));

    const float2* __restrict__ srow = g_stats + pair * TT;
    float* __restrict__ obase = out + (size_t)pair * (TT * HH);

    const int t0 = sub * 24;
#pragma unroll 4
    for (int t = t0; t < t0 + 24; t++) {
        const float4 c  = __ldg(reinterpret_cast<const float4*>(g_C + t * HH + col0));
        const float2 ms = __ldg(srow + t);   // (mean, rstd), warp-uniform

        float4 v;
        v.x = fmaxf(a.x + c.x, 0.f);
        v.y = fmaxf(a.y + c.y, 0.f);
        v.z = fmaxf(a.z + c.z, 0.f);
        v.w = fmaxf(a.w + c.w, 0.f);

        // o = (v - mean) * rstd * gamma + beta  ==  v*kg + kb
        float4 kg, kb, o;
        kg.x = ms.y * gg.x;  kb.x = bb.x - ms.x * kg.x;
        kg.y = ms.y * gg.y;  kb.y = bb.y - ms.x * kg.y;
        kg.z = ms.y * gg.z;  kb.z = bb.z - ms.x * kg.z;
        kg.w = ms.y * gg.w;  kb.w = bb.w - ms.x * kg.w;
        o.x = v.x * kg.x + kb.x;
        o.y = v.y * kg.y + kb.y;
        o.z = v.z * kg.z + kb.z;
        o.w = v.w * kg.w + kb.w;

        __stcs(reinterpret_cast<float4*>(obase + t * HH + col0), o);
    }
}

// ---------------------------------------------------------------------------
// Inputs: 0:x 1:Wp 2:bp 3:Wf 4:bf 5:gamma 6:beta 7:node_emb 8:time_emb
// ---------------------------------------------------------------------------
extern "C" void kernel_launch(void* const* d_in, const int* in_sizes, int n_in,
                              void* d_out, int out_size) {
    const float* x        = (const float*)d_in[0];
    const float* Wp       = (const float*)d_in[1];
    const float* bp       = (const float*)d_in[2];
    const float* Wf       = (const float*)d_in[3];
    const float* bf       = (const float*)d_in[4];
    const float* gamma    = (const float*)d_in[5];
    const float* beta     = (const float*)d_in[6];
    const float* node_emb = (const float*)d_in[7];
    const float* time_emb = (const float*)d_in[8];
    float* out = (float*)d_out;

    prep_kernel<<<2 * TT + NN + 1, 512>>>(Wp, bp, Wf, bf, node_emb, time_emb);
    gemmA_kernel<<<NPAIR / 16, 256>>>(x);
    stats_kernel<<<NPAIR, 128>>>();
    store_kernel<<<NPAIR / 2, 256>>>(gamma, beta, out);
}

// round 12
// speedup vs baseline: 1.2128x; 1.2128x over previous
#include <cuda_runtime.h>
#include <cstdint>

// (B, N, T, H) = (16, 256, 96, 128)
#define BB 16
#define NN 256
#define TT 96
#define HH 128
#define EPS 1e-5f
#define NPAIR (BB * NN)        // 4096

// Scratch (static __device__ — allocation-free)
__device__ float g_C[TT * HH];        // time_emb @ W3            (48 KB)
__device__ float g_nodeS[NN * HH];    // node_emb @ W2            (128 KB)
__device__ float g_Wf[TT * HH];       // Wp @ W1  (fused proj)    (48 KB)
__device__ float g_bias[HH];          // bp @ W1 + bf
__device__ float g_A[NPAIR * HH];     // x@Wf + bias + nodeS      (2 MB)

// ---------------------------------------------------------------------------
// Prep kernel v2: 113 blocks x 512 threads. Each block computes FOUR output
// rows against ONE read of its 64 KB weight matrix (4-way split-K across
// thread quarters) -> W L2 traffic 113 x 64 KB = 7 MB (was 28 MB).
//   r in [0,24)    : g_C rows 4r..4r+3       (time_emb @ W3)
//   r in [24,48)   : g_Wf rows 4(r-24)..+3   (Wp @ W1)
//   r in [48,112)  : g_nodeS rows 4(r-48)..+3 (node_emb @ W2)
//   r == 112       : g_bias                   (bp @ W1 + bf)
// ---------------------------------------------------------------------------
__global__ __launch_bounds__(512) void prep_kernel(
    const float* __restrict__ Wp,
    const float* __restrict__ bp,
    const float* __restrict__ Wf,
    const float* __restrict__ bf,
    const float* __restrict__ node_emb,
    const float* __restrict__ time_emb) {

    __shared__ float vsh[4][HH];
    __shared__ float partial[4][4][HH];   // [p][row][k], 8 KB

    const int r   = blockIdx.x;
    const int tid = threadIdx.x;
    const int k   = tid & (HH - 1);
    const int p   = tid >> 7;             // 0..3

    const float* __restrict__ W;
    const float* __restrict__ vbase;
    int row0, nrows;
    if (r < 24)        { W = Wf + 2*HH*HH; vbase = time_emb; row0 = 4*r;        nrows = 4; }
    else if (r < 48)   { W = Wf;           vbase = Wp;       row0 = 4*(r-24);   nrows = 4; }
    else if (r < 112)  { W = Wf + HH*HH;   vbase = node_emb; row0 = 4*(r-48);   nrows = 4; }
    else               { W = Wf;           vbase = bp;       row0 = 0;          nrows = 1; }

    // stage the 4 (or 1) source vectors
    {
        const int i = tid >> 7;           // row within group
        if (i < nrows) vsh[i][k] = vbase[(row0 + i) * HH + k];
        else           vsh[i][k] = 0.f;
    }
    __syncthreads();

    float acc0 = 0.f, acc1 = 0.f, acc2 = 0.f, acc3 = 0.f;
    const int h0 = p * 32;
#pragma unroll
    for (int hh = 0; hh < 32; hh++) {
        const int h  = h0 + hh;
        const float wv = W[h * HH + k];   // coalesced over k, read ONCE per block
        acc0 += vsh[0][h] * wv;
        acc1 += vsh[1][h] * wv;
        acc2 += vsh[2][h] * wv;
        acc3 += vsh[3][h] * wv;
    }
    partial[p][0][k] = acc0;
    partial[p][1][k] = acc1;
    partial[p][2][k] = acc2;
    partial[p][3][k] = acc3;
    __syncthreads();

    // combine: 512 threads cover 4 rows x 128 cols
    {
        const int i = tid >> 7;
        if (i < nrows) {
            const float s = partial[0][i][k] + partial[1][i][k]
                          + partial[2][i][k] + partial[3][i][k];
            const int row = row0 + i;
            if (r < 24)       g_C[row * HH + k] = s;
            else if (r < 48)  g_Wf[row * HH + k] = s;
            else if (r < 112) g_nodeS[row * HH + k] = s;
            else              g_bias[k] = s + bf[k];
        }
    }
}

// ---------------------------------------------------------------------------
// GEMM-A kernel: g_A[pair,k] = bias[k] + nodeS[pair&255,k]
//                            + sum_t x[pair,t] * Wfused[t,k]
// 256 blocks x 256 threads, 16 pairs per block, 8 pairs x 1 col per thread.
// ---------------------------------------------------------------------------
__global__ __launch_bounds__(256) void gemmA_kernel(const float* __restrict__ x) {
    __shared__ float xsT[TT][16];     // transposed x tile, 6 KB

    const int pair0 = blockIdx.x * 16;
    const int tid   = threadIdx.x;

    for (int idx = tid; idx < 16 * TT; idx += 256) {
        const int pl = idx / TT;
        const int t  = idx - pl * TT;
        xsT[t][pl] = x[(size_t)(pair0 + pl) * TT + t];
    }
    __syncthreads();

    const int k   = tid & (HH - 1);
    const int pl0 = (tid >> 7) * 8;   // 0 or 8

    float acc[8] = {0.f, 0.f, 0.f, 0.f, 0.f, 0.f, 0.f, 0.f};
#pragma unroll 4
    for (int t = 0; t < TT; t++) {
        const float wv = g_Wf[t * HH + k];
        const float4 xa = *reinterpret_cast<const float4*>(&xsT[t][pl0]);
        const float4 xb = *reinterpret_cast<const float4*>(&xsT[t][pl0 + 4]);
        acc[0] += wv * xa.x;  acc[1] += wv * xa.y;
        acc[2] += wv * xa.z;  acc[3] += wv * xa.w;
        acc[4] += wv * xb.x;  acc[5] += wv * xb.y;
        acc[6] += wv * xb.z;  acc[7] += wv * xb.w;
    }

    const float bias = __ldg(g_bias + k);
#pragma unroll
    for (int pl = 0; pl < 8; pl++) {
        const int pair = pair0 + pl0 + pl;
        const int n    = pair & (NN - 1);
        g_A[(size_t)pair * HH + k] = acc[pl] + bias + __ldg(g_nodeS + n * HH + k);
    }
}

// ---------------------------------------------------------------------------
// Main fused kernel: 2048 blocks x 256 threads (8 warps), 2 pairs per block,
// 4 warps per pair, warp owns 24 consecutive rows. NO block-level syncs.
//
// Phase A (stats, warp-local): 12 passes x 2 rows in the 16-lane layout
//   (lane il owns cols {4il, 64+4il}); 4-round shfl butterfly; (mean,rstd)
//   -> smem sstats[warp][row]. Only __syncwarp after.
// Phase B (store, feed-forward): 24 iterations in full-row layout (lane l
//   owns cols 4l..4l+3): 1 L1-hot C LDG.128 + 1 broadcast stats LDS.64 +
//   ~15 ALU + 1 __stcs STG.128. Zero cross-lane deps -> stores issue
//   back-to-back, exactly like the 34.6us pure store kernel. Warps across
//   CTAs sit in different phases, hiding the shfl work under store issue.
// ---------------------------------------------------------------------------
__global__ __launch_bounds__(256, 4) void gpe_main_kernel(
    const float* __restrict__ gamma,
    const float* __restrict__ beta,
    float* __restrict__ out) {

    __shared__ float2 sstats[8][24];    // 1.5 KB

    const int tid  = threadIdx.x;
    const int w    = tid >> 5;
    const int l    = tid & 31;
    const int pair = blockIdx.x * 2 + (w >> 2);
    const int sub  = w & 3;
    const int t0   = sub * 24;

    const float* __restrict__ arow = g_A + (size_t)pair * HH;

    // ---- Phase A: stats for this warp's 24 rows ----
    {
        const int rgrp = l >> 4;
        const int il   = l & 15;
        const int c16  = 4 * il;

        const float4 a0 = __ldg(reinterpret_cast<const float4*>(arow + c16));
        const float4 a1 = __ldg(reinterpret_cast<const float4*>(arow + 64 + c16));

#pragma unroll 3
        for (int p = 0; p < 12; p++) {
            const int row = t0 + 2 * p + rgrp;
            const float* __restrict__ crow = g_C + row * HH;
            const float4 c0 = __ldg(reinterpret_cast<const float4*>(crow + c16));
            const float4 c1 = __ldg(reinterpret_cast<const float4*>(crow + 64 + c16));

            float4 v0, v1;
            v0.x = fmaxf(a0.x + c0.x, 0.f);
            v0.y = fmaxf(a0.y + c0.y, 0.f);
            v0.z = fmaxf(a0.z + c0.z, 0.f);
            v0.w = fmaxf(a0.w + c0.w, 0.f);
            v1.x = fmaxf(a1.x + c1.x, 0.f);
            v1.y = fmaxf(a1.y + c1.y, 0.f);
            v1.z = fmaxf(a1.z + c1.z, 0.f);
            v1.w = fmaxf(a1.w + c1.w, 0.f);

            float s1 = v0.x + v0.y + v0.z + v0.w
                     + v1.x + v1.y + v1.z + v1.w;
            float s2 = v0.x * v0.x + v0.y * v0.y + v0.z * v0.z + v0.w * v0.w
                     + v1.x * v1.x + v1.y * v1.y + v1.z * v1.z + v1.w * v1.w;

#pragma unroll
            for (int off = 1; off < 16; off <<= 1) {
                s1 += __shfl_xor_sync(0xffffffffu, s1, off);
                s2 += __shfl_xor_sync(0xffffffffu, s2, off);
            }

            if (il == 0) {
                const float mean = s1 * (1.f / HH);
                const float var  = s2 * (1.f / HH) - mean * mean;
                sstats[w][2 * p + rgrp] = make_float2(mean, rsqrtf(var + EPS));
            }
        }
    }
    __syncwarp();

    // ---- Phase B: pure feed-forward stores ----
    {
        const int col0 = 4 * l;       // full 128-wide row across the warp

        const float4 a  = __ldg(reinterpret_cast<const float4*>(arow + col0));
        const float4 gg = __ldg(reinterpret_cast<const float4*>(gamma + col0));
        const float4 bb = __ldg(reinterpret_cast<const float4*>(beta + col0));

        float* __restrict__ obase = out + (size_t)pair * (TT * HH);

#pragma unroll 4
        for (int i = 0; i < 24; i++) {
            const int t = t0 + i;
            const float4 c  = __ldg(reinterpret_cast<const float4*>(g_C + t * HH + col0));
            const float2 ms = sstats[w][i];   // warp-uniform broadcast

            float4 v;
            v.x = fmaxf(a.x + c.x, 0.f);
            v.y = fmaxf(a.y + c.y, 0.f);
            v.z = fmaxf(a.z + c.z, 0.f);
            v.w = fmaxf(a.w + c.w, 0.f);

            // o = (v - mean)*rstd*gamma + beta == v*kg + kb
            float4 kg, kb, o;
            kg.x = ms.y * gg.x;  kb.x = bb.x - ms.x * kg.x;
            kg.y = ms.y * gg.y;  kb.y = bb.y - ms.x * kg.y;
            kg.z = ms.y * gg.z;  kb.z = bb.z - ms.x * kg.z;
            kg.w = ms.y * gg.w;  kb.w = bb.w - ms.x * kg.w;
            o.x = v.x * kg.x + kb.x;
            o.y = v.y * kg.y + kb.y;
            o.z = v.z * kg.z + kb.z;
            o.w = v.w * kg.w + kb.w;

            __stcs(reinterpret_cast<float4*>(obase + t * HH + col0), o);
        }
    }
}

// ---------------------------------------------------------------------------
// Inputs: 0:x 1:Wp 2:bp 3:Wf 4:bf 5:gamma 6:beta 7:node_emb 8:time_emb
// ---------------------------------------------------------------------------
extern "C" void kernel_launch(void* const* d_in, const int* in_sizes, int n_in,
                              void* d_out, int out_size) {
    const float* x        = (const float*)d_in[0];
    const float* Wp       = (const float*)d_in[1];
    const float* bp       = (const float*)d_in[2];
    const float* Wf       = (const float*)d_in[3];
    const float* bf       = (const float*)d_in[4];
    const float* gamma    = (const float*)d_in[5];
    const float* beta     = (const float*)d_in[6];
    const float* node_emb = (const float*)d_in[7];
    const float* time_emb = (const float*)d_in[8];
    float* out = (float*)d_out;

    prep_kernel<<<113, 512>>>(Wp, bp, Wf, bf, node_emb, time_emb);
    gemmA_kernel<<<NPAIR / 16, 256>>>(x);
    gpe_main_kernel<<<NPAIR / 2, 256>>>(gamma, beta, out);
}

// round 13
// speedup vs baseline: 1.3577x; 1.1195x over previous
#include <cuda_runtime.h>
#include <cstdint>

// (B, N, T, H) = (16, 256, 96, 128)
#define BB 16
#define NN 256
#define TT 96
#define HH 128
#define EPS 1e-5f
#define NPAIR (BB * NN)        // 4096

// Scratch (static __device__ — allocation-free)
__device__ float g_C[TT * HH];        // time_emb @ W3            (48 KB)
__device__ float g_nodeS[NN * HH];    // node_emb @ W2            (128 KB)
__device__ float g_Wf[TT * HH];       // Wp @ W1  (fused proj)    (48 KB)
__device__ float g_bias[HH];          // bp @ W1 + bf
__device__ float g_A[NPAIR * HH];     // x@Wf + bias + nodeS      (2 MB)

// ---------------------------------------------------------------------------
// Prep kernel v3: latency-optimized. 1796 blocks x 256 threads.
// block = one (row, column-quarter): r = bid>>2 (449 rows), q = bid&3.
// 8-way split-K (warp = one h-sixteenth, 16-FMA chain), smem combine by
// warp 0. ~4x shorter critical path and 4x more blocks than v1.
//   r in [0,96)    : g_C[r]        = time_emb[r] @ W3
//   r in [96,192)  : g_Wf[r-96]    = Wp[r-96]    @ W1
//   r in [192,448) : g_nodeS[r-192]= node_emb[..]@ W2
//   r == 448       : g_bias        = bp @ W1 + bf
// ---------------------------------------------------------------------------
__global__ __launch_bounds__(256) void prep_kernel(
    const float* __restrict__ Wp,
    const float* __restrict__ bp,
    const float* __restrict__ Wf,
    const float* __restrict__ bf,
    const float* __restrict__ node_emb,
    const float* __restrict__ time_emb) {

    __shared__ float vsh[HH];
    __shared__ float part[8][33];      // padded: (i*33+lane)%32 conflict-free

    const int q    = blockIdx.x & 3;
    const int r    = blockIdx.x >> 2;
    const int lane = threadIdx.x & 31;
    const int wp   = threadIdx.x >> 5;     // 0..7
    const int k    = q * 32 + lane;

    const float* __restrict__ v;
    const float* __restrict__ W;
    if (r < TT)               { v = time_emb + r * HH;          W = Wf + 2 * HH * HH; }
    else if (r < 2 * TT)      { v = Wp + (r - TT) * HH;         W = Wf; }
    else if (r < 2 * TT + NN) { v = node_emb + (r - 2*TT) * HH; W = Wf + HH * HH; }
    else                      { v = bp;                         W = Wf; }

    if (threadIdx.x < HH) vsh[threadIdx.x] = v[threadIdx.x];
    __syncthreads();

    float acc = 0.f;
    const int h0 = wp * 16;
#pragma unroll
    for (int hh = 0; hh < 16; hh++) {
        const int h = h0 + hh;
        acc += vsh[h] * W[h * HH + k];     // warp reads 128B line
    }
    part[wp][lane] = acc;
    __syncthreads();

    if (threadIdx.x < 32) {
        float s = 0.f;
#pragma unroll
        for (int i = 0; i < 8; i++) s += part[i][threadIdx.x];
        const int kk = q * 32 + threadIdx.x;
        if (r < TT)               g_C[r * HH + kk] = s;
        else if (r < 2 * TT)      g_Wf[(r - TT) * HH + kk] = s;
        else if (r < 2 * TT + NN) g_nodeS[(r - 2 * TT) * HH + kk] = s;
        else                      g_bias[kk] = s + bf[kk];
    }
}

// ---------------------------------------------------------------------------
// GEMM-A kernel: g_A[pair,k] = bias[k] + nodeS[pair&255,k]
//                            + sum_t x[pair,t] * Wfused[t,k]
// 256 blocks x 256 threads, 16 pairs per block, 8 pairs x 1 col per thread.
// ---------------------------------------------------------------------------
__global__ __launch_bounds__(256) void gemmA_kernel(const float* __restrict__ x) {
    __shared__ float xsT[TT][16];     // transposed x tile, 6 KB

    const int pair0 = blockIdx.x * 16;
    const int tid   = threadIdx.x;

    for (int idx = tid; idx < 16 * TT; idx += 256) {
        const int pl = idx / TT;
        const int t  = idx - pl * TT;
        xsT[t][pl] = x[(size_t)(pair0 + pl) * TT + t];
    }
    __syncthreads();

    const int k   = tid & (HH - 1);
    const int pl0 = (tid >> 7) * 8;   // 0 or 8

    float acc[8] = {0.f, 0.f, 0.f, 0.f, 0.f, 0.f, 0.f, 0.f};
#pragma unroll 4
    for (int t = 0; t < TT; t++) {
        const float wv = g_Wf[t * HH + k];
        const float4 xa = *reinterpret_cast<const float4*>(&xsT[t][pl0]);
        const float4 xb = *reinterpret_cast<const float4*>(&xsT[t][pl0 + 4]);
        acc[0] += wv * xa.x;  acc[1] += wv * xa.y;
        acc[2] += wv * xa.z;  acc[3] += wv * xa.w;
        acc[4] += wv * xb.x;  acc[5] += wv * xb.y;
        acc[6] += wv * xb.z;  acc[7] += wv * xb.w;
    }

    const float bias = __ldg(g_bias + k);
#pragma unroll
    for (int pl = 0; pl < 8; pl++) {
        const int pair = pair0 + pl0 + pl;
        const int n    = pair & (NN - 1);
        g_A[(size_t)pair * HH + k] = acc[pl] + bias + __ldg(g_nodeS + n * HH + k);
    }
}

// ---------------------------------------------------------------------------
// Main kernel (R9 body, occupancy 4->5): 4096 blocks x 256 threads, one
// (b,n) pair per block. No smem, no __syncthreads. 16 lanes per row, 2 rows
// per warp per pass (6 passes = 96 rows). Lane il owns cols {4il..+4} and
// {64+4il..+4}; every STG.128 across the warp covers two contiguous 256B
// row segments. A slice + gamma/beta live in registers; C (48 KB) streams
// from L1. Row mean/var via 4-round shfl butterfly. __stcs stores.
// ---------------------------------------------------------------------------
__global__ __launch_bounds__(256, 5) void gpe_main_kernel(
    const float* __restrict__ gamma,
    const float* __restrict__ beta,
    float* __restrict__ out) {

    const int pair = blockIdx.x;
    const int tid  = threadIdx.x;
    const int w    = tid >> 5;
    const int l    = tid & 31;
    const int rgrp = l >> 4;
    const int il   = l & 15;
    const int col0 = 4 * il;
    const int r0   = w * 2 + rgrp;    // base row; passes add 16

    // Per-pair A slice (written by gemmA_kernel; 2 MB table, L2-hot)
    const float4 a0 = __ldg(reinterpret_cast<const float4*>(g_A + (size_t)pair * HH + col0));
    const float4 a1 = __ldg(reinterpret_cast<const float4*>(g_A + (size_t)pair * HH + 64 + col0));

    const float4 gg0 = __ldg(reinterpret_cast<const float4*>(gamma + col0));
    const float4 gg1 = __ldg(reinterpret_cast<const float4*>(gamma + 64 + col0));
    const float4 bb0 = __ldg(reinterpret_cast<const float4*>(beta + col0));
    const float4 bb1 = __ldg(reinterpret_cast<const float4*>(beta + 64 + col0));

    float* __restrict__ obase = out + (size_t)pair * (TT * HH);

#pragma unroll
    for (int pass = 0; pass < 6; pass++) {
        const int row = pass * 16 + r0;
        const float* __restrict__ crow = g_C + row * HH;
        const float4 c0 = __ldg(reinterpret_cast<const float4*>(crow + col0));
        const float4 c1 = __ldg(reinterpret_cast<const float4*>(crow + 64 + col0));

        float4 v0, v1;
        v0.x = fmaxf(a0.x + c0.x, 0.f);
        v0.y = fmaxf(a0.y + c0.y, 0.f);
        v0.z = fmaxf(a0.z + c0.z, 0.f);
        v0.w = fmaxf(a0.w + c0.w, 0.f);
        v1.x = fmaxf(a1.x + c1.x, 0.f);
        v1.y = fmaxf(a1.y + c1.y, 0.f);
        v1.z = fmaxf(a1.z + c1.z, 0.f);
        v1.w = fmaxf(a1.w + c1.w, 0.f);

        float s1 = v0.x + v0.y + v0.z + v0.w
                 + v1.x + v1.y + v1.z + v1.w;
        float s2 = v0.x * v0.x + v0.y * v0.y + v0.z * v0.z + v0.w * v0.w
                 + v1.x * v1.x + v1.y * v1.y + v1.z * v1.z + v1.w * v1.w;

#pragma unroll
        for (int off = 1; off < 16; off <<= 1) {
            s1 += __shfl_xor_sync(0xffffffffu, s1, off);
            s2 += __shfl_xor_sync(0xffffffffu, s2, off);
        }

        const float mean = s1 * (1.f / HH);
        const float var  = s2 * (1.f / HH) - mean * mean;
        const float rstd = rsqrtf(var + EPS);

        float4 o0, o1;
        o0.x = (v0.x - mean) * rstd * gg0.x + bb0.x;
        o0.y = (v0.y - mean) * rstd * gg0.y + bb0.y;
        o0.z = (v0.z - mean) * rstd * gg0.z + bb0.z;
        o0.w = (v0.w - mean) * rstd * gg0.w + bb0.w;
        o1.x = (v1.x - mean) * rstd * gg1.x + bb1.x;
        o1.y = (v1.y - mean) * rstd * gg1.y + bb1.y;
        o1.z = (v1.z - mean) * rstd * gg1.z + bb1.z;
        o1.w = (v1.w - mean) * rstd * gg1.w + bb1.w;

        float* __restrict__ orow = obase + row * HH;
        __stcs(reinterpret_cast<float4*>(orow + col0), o0);
        __stcs(reinterpret_cast<float4*>(orow + 64 + col0), o1);
    }
}

// ---------------------------------------------------------------------------
// Inputs: 0:x 1:Wp 2:bp 3:Wf 4:bf 5:gamma 6:beta 7:node_emb 8:time_emb
// ---------------------------------------------------------------------------
extern "C" void kernel_launch(void* const* d_in, const int* in_sizes, int n_in,
                              void* d_out, int out_size) {
    const float* x        = (const float*)d_in[0];
    const float* Wp       = (const float*)d_in[1];
    const float* bp       = (const float*)d_in[2];
    const float* Wf       = (const float*)d_in[3];
    const float* bf       = (const float*)d_in[4];
    const float* gamma    = (const float*)d_in[5];
    const float* beta     = (const float*)d_in[6];
    const float* node_emb = (const float*)d_in[7];
    const float* time_emb = (const float*)d_in[8];
    float* out = (float*)d_out;

    prep_kernel<<<(2 * TT + NN + 1) * 4, 256>>>(Wp, bp, Wf, bf, node_emb, time_emb);
    gemmA_kernel<<<NPAIR / 16, 256>>>(x);
    gpe_main_kernel<<<NPAIR, 256>>>(gamma, beta, out);
}

// round 14
// speedup vs baseline: 1.3586x; 1.0007x over previous
#include <cuda_runtime.h>
#include <cstdint>

// (B, N, T, H) = (16, 256, 96, 128)
#define BB 16
#define NN 256
#define TT 96
#define HH 128
#define EPS 1e-5f
#define NPAIR (BB * NN)        // 4096

// Scratch (static __device__ — allocation-free)
__device__ float g_C[TT * HH];        // time_emb @ W3            (48 KB)
__device__ float g_nodeS[NN * HH];    // node_emb @ W2            (128 KB)
__device__ float g_Wf[TT * HH];       // Wp @ W1  (fused proj)    (48 KB)
__device__ float g_bias[HH];          // bp @ W1 + bf
__device__ float g_A[NPAIR * HH];     // x@Wf + bias + nodeS      (2 MB)

// ---------------------------------------------------------------------------
// Prep kernel v4: traffic- AND latency-aware. 226 blocks x 256 threads.
// Block = (row-group g = bid>>1 of 4 output rows) x (k-half q = bid&1).
// Thread (k = q*64 + tid&63, p = tid>>6) accumulates 4 rows over its
// h-quarter [32p, 32p+32): 32 fully-unrolled LDGs (MLP~32 hides cold-DRAM
// latency) x 4 FMA. W traffic: 226 x 32 KB = 7 MB (v3 read 28 MB).
//   g in [0,24)    : g_C rows 4g..+3        (time_emb @ W3)
//   g in [24,48)   : g_Wf rows 4(g-24)..+3  (Wp @ W1)
//   g in [48,112)  : g_nodeS rows 4(g-48)..+3 (node_emb @ W2)
//   g == 112       : g_bias                  (bp @ W1 + bf)
// ---------------------------------------------------------------------------
__global__ __launch_bounds__(256) void prep_kernel(
    const float* __restrict__ Wp,
    const float* __restrict__ bp,
    const float* __restrict__ Wf,
    const float* __restrict__ bf,
    const float* __restrict__ node_emb,
    const float* __restrict__ time_emb) {

    __shared__ float vsh[4][HH];          // 4 source rows
    __shared__ float part[4][4][64];      // [p][row][k_local], 4 KB

    const int q   = blockIdx.x & 1;
    const int g   = blockIdx.x >> 1;
    const int tid = threadIdx.x;
    const int kl  = tid & 63;
    const int p   = tid >> 6;             // 0..3
    const int k   = q * 64 + kl;

    const float* __restrict__ W;
    const float* __restrict__ vbase;
    int row0, nrows;
    if (g < 24)       { W = Wf + 2*HH*HH; vbase = time_emb; row0 = 4*g;      nrows = 4; }
    else if (g < 48)  { W = Wf;           vbase = Wp;       row0 = 4*(g-24); nrows = 4; }
    else if (g < 112) { W = Wf + HH*HH;   vbase = node_emb; row0 = 4*(g-48); nrows = 4; }
    else              { W = Wf;           vbase = bp;       row0 = 0;        nrows = 1; }

    // stage source rows (zero the unused ones)
#pragma unroll
    for (int j = 0; j < 2; j++) {
        const int idx = tid + 256 * j;    // 0..511
        const int r   = idx >> 7;
        const int h   = idx & (HH - 1);
        vsh[r][h] = (r < nrows) ? vbase[(row0 + r) * HH + h] : 0.f;
    }
    __syncthreads();

    float a0 = 0.f, a1 = 0.f, a2 = 0.f, a3 = 0.f;
    const int h0 = p * 32;
#pragma unroll
    for (int hh = 0; hh < 32; hh++) {
        const int h = h0 + hh;
        const float wv = W[h * HH + k];   // 32 independent LDGs, coalesced
        a0 += vsh[0][h] * wv;
        a1 += vsh[1][h] * wv;
        a2 += vsh[2][h] * wv;
        a3 += vsh[3][h] * wv;
    }
    part[p][0][kl] = a0;
    part[p][1][kl] = a1;
    part[p][2][kl] = a2;
    part[p][3][kl] = a3;
    __syncthreads();

    // combine: 256 threads = 4 rows x 64 cols
    {
        const int r = tid >> 6;           // 0..3
        if (r < nrows) {
            const float s = part[0][r][kl] + part[1][r][kl]
                          + part[2][r][kl] + part[3][r][kl];
            const int row = row0 + r;
            if (g < 24)       g_C[row * HH + k] = s;
            else if (g < 48)  g_Wf[row * HH + k] = s;
            else if (g < 112) g_nodeS[row * HH + k] = s;
            else              g_bias[k] = s + bf[k];
        }
    }
}

// ---------------------------------------------------------------------------
// GEMM-A kernel: g_A[pair,k] = bias[k] + nodeS[pair&255,k]
//                            + sum_t x[pair,t] * Wfused[t,k]
// 256 blocks x 256 threads, 16 pairs per block, 8 pairs x 1 col per thread.
// ---------------------------------------------------------------------------
__global__ __launch_bounds__(256) void gemmA_kernel(const float* __restrict__ x) {
    __shared__ float xsT[TT][16];     // transposed x tile, 6 KB

    const int pair0 = blockIdx.x * 16;
    const int tid   = threadIdx.x;

    for (int idx = tid; idx < 16 * TT; idx += 256) {
        const int pl = idx / TT;
        const int t  = idx - pl * TT;
        xsT[t][pl] = x[(size_t)(pair0 + pl) * TT + t];
    }
    __syncthreads();

    const int k   = tid & (HH - 1);
    const int pl0 = (tid >> 7) * 8;   // 0 or 8

    float acc[8] = {0.f, 0.f, 0.f, 0.f, 0.f, 0.f, 0.f, 0.f};
#pragma unroll 4
    for (int t = 0; t < TT; t++) {
        const float wv = g_Wf[t * HH + k];
        const float4 xa = *reinterpret_cast<const float4*>(&xsT[t][pl0]);
        const float4 xb = *reinterpret_cast<const float4*>(&xsT[t][pl0 + 4]);
        acc[0] += wv * xa.x;  acc[1] += wv * xa.y;
        acc[2] += wv * xa.z;  acc[3] += wv * xa.w;
        acc[4] += wv * xb.x;  acc[5] += wv * xb.y;
        acc[6] += wv * xb.z;  acc[7] += wv * xb.w;
    }

    const float bias = __ldg(g_bias + k);
#pragma unroll
    for (int pl = 0; pl < 8; pl++) {
        const int pair = pair0 + pl0 + pl;
        const int n    = pair & (NN - 1);
        g_A[(size_t)pair * HH + k] = acc[pl] + bias + __ldg(g_nodeS + n * HH + k);
    }
}

// ---------------------------------------------------------------------------
// Main kernel (unchanged from R13): 4096 blocks x 256 threads, one (b,n)
// pair per block. No smem, no __syncthreads. 16 lanes per row, 2 rows per
// warp per pass (6 passes = 96 rows). Lane il owns cols {4il..+4} and
// {64+4il..+4}; every STG.128 across the warp covers two contiguous 256B
// row segments. A slice + gamma/beta live in registers; C (48 KB) streams
// from L1. Row mean/var via 4-round shfl butterfly. __stcs stores.
// ---------------------------------------------------------------------------
__global__ __launch_bounds__(256, 5) void gpe_main_kernel(
    const float* __restrict__ gamma,
    const float* __restrict__ beta,
    float* __restrict__ out) {

    const int pair = blockIdx.x;
    const int tid  = threadIdx.x;
    const int w    = tid >> 5;
    const int l    = tid & 31;
    const int rgrp = l >> 4;
    const int il   = l & 15;
    const int col0 = 4 * il;
    const int r0   = w * 2 + rgrp;    // base row; passes add 16

    const float4 a0 = __ldg(reinterpret_cast<const float4*>(g_A + (size_t)pair * HH + col0));
    const float4 a1 = __ldg(reinterpret_cast<const float4*>(g_A + (size_t)pair * HH + 64 + col0));

    const float4 gg0 = __ldg(reinterpret_cast<const float4*>(gamma + col0));
    const float4 gg1 = __ldg(reinterpret_cast<const float4*>(gamma + 64 + col0));
    const float4 bb0 = __ldg(reinterpret_cast<const float4*>(beta + col0));
    const float4 bb1 = __ldg(reinterpret_cast<const float4*>(beta + 64 + col0));

    float* __restrict__ obase = out + (size_t)pair * (TT * HH);

#pragma unroll
    for (int pass = 0; pass < 6; pass++) {
        const int row = pass * 16 + r0;
        const float* __restrict__ crow = g_C + row * HH;
        const float4 c0 = __ldg(reinterpret_cast<const float4*>(crow + col0));
        const float4 c1 = __ldg(reinterpret_cast<const float4*>(crow + 64 + col0));

        float4 v0, v1;
        v0.x = fmaxf(a0.x + c0.x, 0.f);
        v0.y = fmaxf(a0.y + c0.y, 0.f);
        v0.z = fmaxf(a0.z + c0.z, 0.f);
        v0.w = fmaxf(a0.w + c0.w, 0.f);
        v1.x = fmaxf(a1.x + c1.x, 0.f);
        v1.y = fmaxf(a1.y + c1.y, 0.f);
        v1.z = fmaxf(a1.z + c1.z, 0.f);
        v1.w = fmaxf(a1.w + c1.w, 0.f);

        float s1 = v0.x + v0.y + v0.z + v0.w
                 + v1.x + v1.y + v1.z + v1.w;
        float s2 = v0.x * v0.x + v0.y * v0.y + v0.z * v0.z + v0.w * v0.w
                 + v1.x * v1.x + v1.y * v1.y + v1.z * v1.z + v1.w * v1.w;

#pragma unroll
        for (int off = 1; off < 16; off <<= 1) {
            s1 += __shfl_xor_sync(0xffffffffu, s1, off);
            s2 += __shfl_xor_sync(0xffffffffu, s2, off);
        }

        const float mean = s1 * (1.f / HH);
        const float var  = s2 * (1.f / HH) - mean * mean;
        const float rstd = rsqrtf(var + EPS);

        float4 o0, o1;
        o0.x = (v0.x - mean) * rstd * gg0.x + bb0.x;
        o0.y = (v0.y - mean) * rstd * gg0.y + bb0.y;
        o0.z = (v0.z - mean) * rstd * gg0.z + bb0.z;
        o0.w = (v0.w - mean) * rstd * gg0.w + bb0.w;
        o1.x = (v1.x - mean) * rstd * gg1.x + bb1.x;
        o1.y = (v1.y - mean) * rstd * gg1.y + bb1.y;
        o1.z = (v1.z - mean) * rstd * gg1.z + bb1.z;
        o1.w = (v1.w - mean) * rstd * gg1.w + bb1.w;

        float* __restrict__ orow = obase + row * HH;
        __stcs(reinterpret_cast<float4*>(orow + col0), o0);
        __stcs(reinterpret_cast<float4*>(orow + 64 + col0), o1);
    }
}

// ---------------------------------------------------------------------------
// Inputs: 0:x 1:Wp 2:bp 3:Wf 4:bf 5:gamma 6:beta 7:node_emb 8:time_emb
// ---------------------------------------------------------------------------
extern "C" void kernel_launch(void* const* d_in, const int* in_sizes, int n_in,
                              void* d_out, int out_size) {
    const float* x        = (const float*)d_in[0];
    const float* Wp       = (const float*)d_in[1];
    const float* bp       = (const float*)d_in[2];
    const float* Wf       = (const float*)d_in[3];
    const float* bf       = (const float*)d_in[4];
    const float* gamma    = (const float*)d_in[5];
    const float* beta     = (const float*)d_in[6];
    const float* node_emb = (const float*)d_in[7];
    const float* time_emb = (const float*)d_in[8];
    float* out = (float*)d_out;

    prep_kernel<<<226, 256>>>(Wp, bp, Wf, bf, node_emb, time_emb);
    gemmA_kernel<<<NPAIR / 16, 256>>>(x);
    gpe_main_kernel<<<NPAIR, 256>>>(gamma, beta, out);
}